// round 3
// baseline (speedup 1.0000x reference)
#include <cuda_runtime.h>
#include <cstring>

#define Bn 512
#define Tn 512
#define Nn 64

__device__ __forceinline__ unsigned long long fma2(unsigned long long a,
                                                   unsigned long long b,
                                                   unsigned long long c) {
    unsigned long long d;
    asm("fma.rn.f32x2 %0, %1, %2, %3;" : "=l"(d) : "l"(a), "l"(b), "l"(c));
    return d;
}

__device__ __forceinline__ unsigned long long pack2(float x, float y) {
    float2 f; f.x = x; f.y = y;
    unsigned long long u;
    memcpy(&u, &f, 8);
    return u;
}

__global__ void __launch_bounds__(64) crf_kernel(
    const float* __restrict__ inp,    // [B,T,N]
    const float* __restrict__ trans,  // [N,N]
    const int*   __restrict__ tags,   // [B,T]
    const int*   __restrict__ lens,   // [B]
    float*       __restrict__ out)    // [512 (+4096)]
{
    const int b = blockIdx.x;
    const int j = threadIdx.x;

    if (b >= Bn) {
        int idx = (b - Bn) * Nn + j;
        out[Bn + idx] = trans[idx];
        return;
    }

    __shared__ float pbuf[2][Nn];
    __shared__ float red[Nn];

    const int L    = lens[b];
    const int last = (L - 1) > 0 ? (L - 1) : 0;
    const long baseBT = (long)b * Tn;
    const float* __restrict__ erow = inp + baseBT * Nn;

    // ---------------- sequence score (parallel over t) ----------------
    float s = 0.f;
    for (int t = j; t < Tn; t += Nn) {
        if (t < L) {
            int tg = tags[baseBT + t];
            s += erow[t * Nn + tg];
            if (t >= 1) {
                int tp = tags[baseBT + t - 1];
                s += trans[tp * Nn + tg];
            }
        }
    }
    #pragma unroll
    for (int o = 16; o > 0; o >>= 1)
        s += __shfl_down_sync(0xffffffffu, s, o);
    if ((j & 31) == 0) red[j >> 5] = s;
    __syncthreads();
    const float seqscore = red[0] + red[1];
    __syncthreads();

    // ---------------- E column j = exp(trans[:, j]) packed f32x2 ----------------
    unsigned long long E2[Nn / 2];
    #pragma unroll
    for (int i = 0; i < Nn / 2; i++) {
        float e0 = __expf(trans[(2 * i)     * Nn + j]);
        float e1 = __expf(trans[(2 * i + 1) * Nn + j]);
        E2[i] = pack2(e0, e1);
    }

    // ---------------- forward recursion (linear space, exact 2^-k rescale) ----
    float q = __expf(erow[j]);        // q_0 = exp(alpha_0)
    pbuf[0][j] = q;
    int K = 0;                        // accumulated power-of-two scaling
    int buf = 0;

    // one recursion step; EEMIT = exp(emission) register value
#define STEP(EEMIT)                                                       \
    do {                                                                  \
        __syncthreads();                                                  \
        const float4* p4 = reinterpret_cast<const float4*>(pbuf[buf]);    \
        float4 pv0 = p4[0];                                               \
        int eb = (__float_as_int(pv0.x) >> 23) & 0xFF;                    \
        eb = eb < 64 ? 64 : (eb > 190 ? 190 : eb);                        \
        const float sc = __int_as_float((254 - eb) << 23);                \
        K += eb - 127;                                                    \
        unsigned long long a0, a1, a2, a3;                                \
        {                                                                 \
            float4 pw = p4[1];                                            \
            a0 = fma2(pack2(pv0.x, pv0.y), E2[0], 0ull);                  \
            a1 = fma2(pack2(pv0.z, pv0.w), E2[1], 0ull);                  \
            a2 = fma2(pack2(pw.x, pw.y),   E2[2], 0ull);                  \
            a3 = fma2(pack2(pw.z, pw.w),   E2[3], 0ull);                  \
        }                                                                 \
        _Pragma("unroll")                                                 \
        for (int i = 1; i < 8; i++) {                                     \
            float4 pv = p4[2 * i];                                        \
            float4 pw = p4[2 * i + 1];                                    \
            a0 = fma2(pack2(pv.x, pv.y), E2[4 * i + 0], a0);              \
            a1 = fma2(pack2(pv.z, pv.w), E2[4 * i + 1], a1);              \
            a2 = fma2(pack2(pw.x, pw.y), E2[4 * i + 2], a2);              \
            a3 = fma2(pack2(pw.z, pw.w), E2[4 * i + 3], a3);              \
        }                                                                 \
        unsigned long long s01, s23, s03;                                 \
        asm("add.rn.f32x2 %0, %1, %2;" : "=l"(s01) : "l"(a0), "l"(a1));   \
        asm("add.rn.f32x2 %0, %1, %2;" : "=l"(s23) : "l"(a2), "l"(a3));   \
        asm("add.rn.f32x2 %0, %1, %2;" : "=l"(s03) : "l"(s01), "l"(s23)); \
        float2 fs; memcpy(&fs, &s03, 8);                                  \
        const float S = fs.x + fs.y;                                      \
        q = S * (EEMIT) * sc;                                             \
        pbuf[buf ^ 1][j] = q;                                             \
        buf ^= 1;                                                         \
    } while (0)

#define EMLOAD(ROW) erow[(((ROW) < Tn - 1) ? (ROW) : (Tn - 1)) * Nn + j]

    // raw emission pipeline: c* = raw rows t..t+3 (loaded a chunk ago)
    float c0 = EMLOAD(1), c1 = EMLOAD(2), c2 = EMLOAD(3), c3 = EMLOAD(4);

    int t = 1;
    for (; t + 3 <= last; t += 4) {
        // issue next chunk's independent loads (hidden behind this chunk)
        float n0 = EMLOAD(t + 4);
        float n1 = EMLOAD(t + 5);
        float n2 = EMLOAD(t + 6);
        float n3 = EMLOAD(t + 7);
        // convert this chunk's raw emissions (MUFU off the critical path)
        float x0 = __expf(c0), x1 = __expf(c1), x2 = __expf(c2), x3 = __expf(c3);
        STEP(x0);
        STEP(x1);
        STEP(x2);
        STEP(x3);
        c0 = n0; c1 = n1; c2 = n2; c3 = n3;
    }
    // tail (<=3 steps); c0..c2 hold raw rows t..t+2
    if (t <= last) { float x = __expf(c0); STEP(x); t++; }
    if (t <= last) { float x = __expf(c1); STEP(x); t++; }
    if (t <= last) { float x = __expf(c2); STEP(x); t++; }

#undef STEP
#undef EMLOAD

    // ---------------- final log-normalizer ----------------
    __syncthreads();
    red[j] = q;
    __syncthreads();
    if (j == 0) {
        float ss = 0.f;
        #pragma unroll
        for (int i = 0; i < Nn; i++) ss += red[i];
        const float LN2_HI = 0.693145751953125f;      // top bits exact
        const float LN2_LO = 1.428606765330187e-06f;  // remainder
        const float Kf = (float)K;
        const float lognorm = fmaf(Kf, LN2_LO, fmaf(Kf, LN2_HI, __logf(ss)));
        out[b] = seqscore - lognorm;
    }
}

extern "C" void kernel_launch(void* const* d_in, const int* in_sizes, int n_in,
                              void* d_out, int out_size) {
    const float* inp   = (const float*)d_in[0];
    const float* trans = (const float*)d_in[1];
    const int*   tags  = (const int*)d_in[2];
    const int*   lens  = (const int*)d_in[3];
    float* out = (float*)d_out;

    int nblocks = Bn;
    if (out_size >= Bn + Nn * Nn) nblocks += Nn;
    crf_kernel<<<nblocks, Nn>>>(inp, trans, tags, lens, out);
}